// round 1
// baseline (speedup 1.0000x reference)
#include <cuda_runtime.h>
#include <math.h>
#include <stdint.h>

// ---------------- problem-size bounds (N=50000, E=400000 in dataset) ----------
#define MAXN 50176
#define MAXE 400384

// ---------------- device scratch (no mallocs allowed) -------------------------
__device__ float  g_h1  [MAXN * 128];            // layer1 node embeddings [N,4,32]
__device__ float  g_res [MAXN * 128];            // residual (res1 then res2)
__device__ float  g_acc1[MAXN * 128];            // layer1 aggregate -> y -> BN input
__device__ float  g_h2  [(size_t)MAXN * 512];    // layer2 node embeddings [N,4,128]
__device__ float  g_acc2[(size_t)MAXN * 512];    // layer2 aggregate
__device__ float  g_s[MAXN * 4], g_d[MAXN * 4];  // attention src/dst terms
__device__ float  g_amax[MAXN * 4], g_den[MAXN * 4];
__device__ float  g_alpha[MAXE * 4];             // alpha, then exp(alpha-max)
__device__ float  g_e2[MAXE * 4];                // layer2 edge attention term
__device__ double g_colsum[128], g_colsq[128];
__device__ float  g_scale[128], g_shift[128];
__device__ float  g_aew1[64 * 4], g_aew2[64 * 4];
__device__ float  g_eea1[4 * 4],  g_eea2[4 * 4];
__device__ float  g_ne1w1[3 * 128], g_ne2w2[3 * 512];

// ---------------- helpers ------------------------------------------------------
__device__ __forceinline__ void atomicMaxF(float* a, float v) {
    unsigned int b = __float_as_uint(v);
    if (b >> 31) atomicMin((unsigned int*)a, b);   // negative (incl -0): uint-min = float-max
    else         atomicMax((int*)a, (int)b);       // non-negative: int-max = float-max
}

__device__ __forceinline__ void red4(float* p, float a, float b, float c, float d) {
    asm volatile("red.global.add.v4.f32 [%0], {%1,%2,%3,%4};"
                 :: "l"(p), "f"(a), "f"(b), "f"(c), "f"(d) : "memory");
}

// ---------------- init ----------------------------------------------------------
__global__ void k_init1(int N) {
    long i = (long)blockIdx.x * blockDim.x + threadIdx.x;
    long stride = (long)gridDim.x * blockDim.x;
    for (long j = i; j < (long)N * 512; j += stride) g_acc2[j] = 0.f;
    for (long j = i; j < (long)N * 128; j += stride) g_acc1[j] = 0.f;
    for (long j = i; j < (long)N * 4; j += stride) {
        g_den[j] = 0.f;
        g_amax[j] = __int_as_float(0xFF800000);  // -inf
    }
    if (i < 128) { g_colsum[i] = 0.0; g_colsq[i] = 0.0; }
}

__global__ void k_init2(int N) {
    long i = (long)blockIdx.x * blockDim.x + threadIdx.x;
    long stride = (long)gridDim.x * blockDim.x;
    for (long j = i; j < (long)N * 4; j += stride) {
        g_den[j] = 0.f;
        g_amax[j] = __int_as_float(0xFF800000);
    }
}

// ---------------- precompute: fold linear maps ----------------------------------
// aeW[k,h] = sum_c We[k, h*C + c] * a_edge[h,c];  neW[t,:] = ne[t,:] @ W
__global__ void k_pre_a(const float* __restrict__ we1, const float* __restrict__ aedge1,
                        const float* __restrict__ we2, const float* __restrict__ aedge2,
                        const float* __restrict__ ne1, const float* __restrict__ w1,
                        const float* __restrict__ ne2, const float* __restrict__ w2) {
    int i = blockIdx.x * blockDim.x + threadIdx.x;
    if (i < 256) {                       // aeW1: [64,4], C=32
        int k = i >> 2, h = i & 3; float a = 0.f;
        for (int c = 0; c < 32; c++) a += we1[k * 128 + h * 32 + c] * aedge1[h * 32 + c];
        g_aew1[i] = a;
    } else if (i < 512) {                // aeW2: [64,4], C=128
        int j = i - 256; int k = j >> 2, h = j & 3; float a = 0.f;
        for (int c = 0; c < 128; c++) a += we2[k * 512 + h * 128 + c] * aedge2[h * 128 + c];
        g_aew2[j] = a;
    } else if (i < 896) {                // ne1@w1: [3,128]
        int j = i - 512; int t = j >> 7, col = j & 127; float a = 0.f;
        for (int k = 0; k < 32; k++) a += ne1[t * 32 + k] * w1[k * 128 + col];
        g_ne1w1[j] = a;
    } else if (i < 2432) {               // ne2@w2: [3,512]
        int j = i - 896; int t = j >> 9, col = j & 511; float a = 0.f;
        for (int k = 0; k < 128; k++) a += ne2[t * 128 + k] * w2[k * 512 + col];
        g_ne2w2[j] = a;
    }
}

// eeA[t,h] = ee[t,:] @ aeW[:,h]   (depends on k_pre_a)
__global__ void k_pre_b(const float* __restrict__ ee1, const float* __restrict__ ee2) {
    int i = threadIdx.x;
    if (i < 16) {
        int t = i >> 2, h = i & 3; float a = 0.f;
        for (int k = 0; k < 64; k++) a += ee1[t * 64 + k] * g_aew1[k * 4 + h];
        g_eea1[i] = a;
    } else if (i < 32) {
        int j = i - 16; int t = j >> 2, h = j & 3; float a = 0.f;
        for (int k = 0; k < 64; k++) a += ee2[t * 64 + k] * g_aew2[k * 4 + h];
        g_eea2[j] = a;
    }
}

// ---------------- layer 1 GEMM: h1 = x@w1 + (ne1@w1)[nt], res1 = x@wres1 + b1 ----
__global__ void k_gemm1(const float* __restrict__ x, const int* __restrict__ nt,
                        const float* __restrict__ w1, const float* __restrict__ wres1,
                        const float* __restrict__ b1, int N) {
    __shared__ float sW1[32 * 128], sWr[32 * 128], sX[64 * 33];
    int t = threadIdx.x;  // 128
    for (int i = t; i < 32 * 128; i += 128) { sW1[i] = w1[i]; sWr[i] = wres1[i]; }
    int r0 = blockIdx.x * 64;
    for (int i = t; i < 64 * 32; i += 128) {
        int r = i >> 5, k = i & 31; int gr = r0 + r;
        sX[r * 33 + k] = (gr < N) ? x[(size_t)gr * 32 + k] : 0.f;
    }
    __syncthreads();
    float bb = b1[t];
    int rmax = (N - r0 < 64) ? (N - r0) : 64;
    for (int r = 0; r < rmax; r++) {
        float a1 = 0.f, a2 = 0.f;
        #pragma unroll
        for (int k = 0; k < 32; k++) {
            float xv = sX[r * 33 + k];
            a1 += xv * sW1[k * 128 + t];
            a2 += xv * sWr[k * 128 + t];
        }
        int gr = r0 + r;
        g_h1 [(size_t)gr * 128 + t] = a1 + g_ne1w1[nt[gr] * 128 + t];
        g_res[(size_t)gr * 128 + t] = a2 + bb;
    }
}

// ---------------- s/d terms layer 1: s[n,h] = h1[n,h,:]·asrc[h,:]  (C=32) --------
__global__ void k_sd1(const float* __restrict__ asrc, const float* __restrict__ adst, int N) {
    int n = blockIdx.x; if (n >= N) return;
    int t = threadIdx.x;  // 128; t = h*32+c
    float h = g_h1[(size_t)n * 128 + t];
    float ps = h * asrc[t], pd = h * adst[t];
    for (int o = 16; o; o >>= 1) {
        ps += __shfl_xor_sync(0xffffffffu, ps, o);
        pd += __shfl_xor_sync(0xffffffffu, pd, o);
    }
    if ((t & 31) == 0) { int w = t >> 5; g_s[n * 4 + w] = ps; g_d[n * 4 + w] = pd; }
}

// ---------------- edge pass A (layer 1): e1/e2 from edge_attr, alpha1, amax ------
__global__ void k_edgeA1(const int* __restrict__ src, const int* __restrict__ dst,
                         const float* __restrict__ ea, const int* __restrict__ et, int E) {
    int e = blockIdx.x * 8 + (threadIdx.x >> 5); if (e >= E) return;
    int l = threadIdx.x & 31;
    float e1[4] = {0, 0, 0, 0}, e2[4] = {0, 0, 0, 0};
    const float* row = ea + (size_t)e * 64;
    for (int k = l; k < 64; k += 32) {
        float v = row[k];
        #pragma unroll
        for (int h = 0; h < 4; h++) { e1[h] += v * g_aew1[k * 4 + h]; e2[h] += v * g_aew2[k * 4 + h]; }
    }
    #pragma unroll
    for (int h = 0; h < 4; h++)
        for (int o = 16; o; o >>= 1) {
            e1[h] += __shfl_xor_sync(0xffffffffu, e1[h], o);
            e2[h] += __shfl_xor_sync(0xffffffffu, e2[h], o);
        }
    if (l < 4) {
        int s_ = src[e], d_ = dst[e], ty = et[e];
        float a = g_s[s_ * 4 + l] + g_d[d_ * 4 + l] + e1[l] + g_eea1[ty * 4 + l];
        a = (a >= 0.f) ? a : 0.2f * a;
        g_alpha[e * 4 + l] = a;
        atomicMaxF(&g_amax[d_ * 4 + l], a);
        g_e2[e * 4 + l] = e2[l] + g_eea2[ty * 4 + l];
    }
}

// ---------------- edge pass B (both layers): ex = exp(a-max), den += ex ----------
__global__ void k_passB(const int* __restrict__ dst, int E) {
    int i = blockIdx.x * blockDim.x + threadIdx.x;
    if (i >= E * 4) return;
    int e = i >> 2, h = i & 3; int d_ = dst[e];
    float ex = expf(g_alpha[i] - g_amax[d_ * 4 + h]);
    g_alpha[i] = ex;
    atomicAdd(&g_den[d_ * 4 + h], ex);
}

// ---------------- edge aggregate layer 1: acc1[dst] += h1[src]*coef  -------------
__global__ void k_aggr1(const int* __restrict__ src, const int* __restrict__ dst, int E) {
    int e = blockIdx.x * 8 + (threadIdx.x >> 5); if (e >= E) return;
    int l = threadIdx.x & 31;
    int s_ = src[e], d_ = dst[e];
    float cf = 0.f;
    if (l < 4) cf = g_alpha[e * 4 + l] / (g_den[d_ * 4 + l] + 1e-16f);
    float coef = __shfl_sync(0xffffffffu, cf, l >> 3);  // head = (l*4)/32
    float4 hv = *reinterpret_cast<const float4*>(&g_h1[(size_t)s_ * 128 + l * 4]);
    red4(&g_acc1[(size_t)d_ * 128 + l * 4], hv.x * coef, hv.y * coef, hv.z * coef, hv.w * coef);
}

// ---------------- BN stats: y = acc1+res1 (in place), double col sums ------------
__global__ void k_bnstats(int N) {
    int t = threadIdx.x;  // 128
    double s = 0.0, q = 0.0;
    for (int n = blockIdx.x; n < N; n += gridDim.x) {
        float y = g_acc1[(size_t)n * 128 + t] + g_res[(size_t)n * 128 + t];
        g_acc1[(size_t)n * 128 + t] = y;
        s += y; q += (double)y * y;
    }
    atomicAdd(&g_colsum[t], s);
    atomicAdd(&g_colsq[t], q);
}

__global__ void k_bnfin(const float* __restrict__ gamma, const float* __restrict__ beta, int N) {
    int t = threadIdx.x;
    double mu = g_colsum[t] / N;
    double var = g_colsq[t] / N - mu * mu;
    double sc = (double)gamma[t] / sqrt(var + 1e-5);
    g_scale[t] = (float)sc;
    g_shift[t] = (float)((double)beta[t] - mu * sc);
}

// ---------------- layer 2 GEMM: h2 = BN(y)@w2 + (ne2@w2)[nt]; res2 = BN(y)@wres2 + b2
__global__ void k_gemm2(const int* __restrict__ nt, const float* __restrict__ w2,
                        const float* __restrict__ wres2, const float* __restrict__ b2, int N) {
    extern __shared__ float sm[];
    float* sX = sm;               // 64 * 132
    float* sW = sm + 64 * 132;    // 128 * 128
    int t = threadIdx.x;          // 256
    int r0 = blockIdx.x * 64;
    for (int i = t; i < 64 * 128; i += 256) {
        int r = i >> 7, k = i & 127; int gr = r0 + r;
        float v = 0.f;
        if (gr < N) v = g_acc1[(size_t)gr * 128 + k] * g_scale[k] + g_shift[k];
        sX[r * 132 + k] = v;
    }
    int cg = t & 15, rg = t >> 4;
    int rbase = rg * 4, cbase = cg * 8;
    for (int ct = 0; ct < 5; ct++) {
        __syncthreads();
        for (int i = t; i < 128 * 128; i += 256) {
            int k = i >> 7, c = i & 127;
            sW[i] = (ct < 4) ? w2[(size_t)k * 512 + ct * 128 + c] : wres2[(size_t)k * 128 + c];
        }
        __syncthreads();
        float acc[4][8];
        #pragma unroll
        for (int j = 0; j < 4; j++)
            #pragma unroll
            for (int q = 0; q < 8; q++) acc[j][q] = 0.f;
        for (int k = 0; k < 128; k++) {
            float4 wa = *reinterpret_cast<const float4*>(&sW[k * 128 + cbase]);
            float4 wb = *reinterpret_cast<const float4*>(&sW[k * 128 + cbase + 4]);
            #pragma unroll
            for (int j = 0; j < 4; j++) {
                float xv = sX[(rbase + j) * 132 + k];
                acc[j][0] += xv * wa.x; acc[j][1] += xv * wa.y;
                acc[j][2] += xv * wa.z; acc[j][3] += xv * wa.w;
                acc[j][4] += xv * wb.x; acc[j][5] += xv * wb.y;
                acc[j][6] += xv * wb.z; acc[j][7] += xv * wb.w;
            }
        }
        for (int j = 0; j < 4; j++) {
            int gr = r0 + rbase + j; if (gr >= N) continue;
            if (ct < 4) {
                int ty = nt[gr];
                const float* bias = &g_ne2w2[ty * 512 + ct * 128 + cbase];
                float4 o0 = make_float4(acc[j][0] + bias[0], acc[j][1] + bias[1],
                                        acc[j][2] + bias[2], acc[j][3] + bias[3]);
                float4 o1 = make_float4(acc[j][4] + bias[4], acc[j][5] + bias[5],
                                        acc[j][6] + bias[6], acc[j][7] + bias[7]);
                float* dst = &g_h2[(size_t)gr * 512 + ct * 128 + cbase];
                *reinterpret_cast<float4*>(dst) = o0;
                *reinterpret_cast<float4*>(dst + 4) = o1;
            } else {
                const float* bias = &b2[cbase];
                float4 o0 = make_float4(acc[j][0] + bias[0], acc[j][1] + bias[1],
                                        acc[j][2] + bias[2], acc[j][3] + bias[3]);
                float4 o1 = make_float4(acc[j][4] + bias[4], acc[j][5] + bias[5],
                                        acc[j][6] + bias[6], acc[j][7] + bias[7]);
                float* dst = &g_res[(size_t)gr * 128 + cbase];
                *reinterpret_cast<float4*>(dst) = o0;
                *reinterpret_cast<float4*>(dst + 4) = o1;
            }
        }
    }
}

// ---------------- s/d terms layer 2 (C=128): one warp per head -------------------
__global__ void k_sd2(const float* __restrict__ asrc, const float* __restrict__ adst, int N) {
    int n = blockIdx.x; if (n >= N) return;
    int t = threadIdx.x; int w = t >> 5, l = t & 31;
    float ps = 0.f, pd = 0.f;
    const float* hrow = &g_h2[(size_t)n * 512 + w * 128];
    const float* as = asrc + w * 128;
    const float* ad = adst + w * 128;
    for (int c = l; c < 128; c += 32) { float h = hrow[c]; ps += h * as[c]; pd += h * ad[c]; }
    for (int o = 16; o; o >>= 1) {
        ps += __shfl_xor_sync(0xffffffffu, ps, o);
        pd += __shfl_xor_sync(0xffffffffu, pd, o);
    }
    if (l == 0) { g_s[n * 4 + w] = ps; g_d[n * 4 + w] = pd; }
}

// ---------------- edge pass A (layer 2): alpha2 from stored e2, amax -------------
__global__ void k_edgeA2(const int* __restrict__ src, const int* __restrict__ dst, int E) {
    int i = blockIdx.x * blockDim.x + threadIdx.x;
    if (i >= E * 4) return;
    int e = i >> 2, h = i & 3;
    int s_ = src[e], d_ = dst[e];
    float a = g_s[s_ * 4 + h] + g_d[d_ * 4 + h] + g_e2[i];
    a = (a >= 0.f) ? a : 0.2f * a;
    g_alpha[i] = a;
    atomicMaxF(&g_amax[d_ * 4 + h], a);
}

// ---------------- edge aggregate layer 2: acc2[dst] += h2[src]*coef --------------
__global__ void k_aggr2(const int* __restrict__ src, const int* __restrict__ dst, int E) {
    int e = blockIdx.x * 8 + (threadIdx.x >> 5); if (e >= E) return;
    int l = threadIdx.x & 31;
    int s_ = src[e], d_ = dst[e];
    float cf = 0.f;
    if (l < 4) cf = g_alpha[e * 4 + l] / (g_den[d_ * 4 + l] + 1e-16f);
    const float4* hsrc = reinterpret_cast<const float4*>(&g_h2[(size_t)s_ * 512]);
    float* dbase = &g_acc2[(size_t)d_ * 512];
    #pragma unroll
    for (int it = 0; it < 4; it++) {
        int f4 = it * 32 + l;                       // float4 index 0..127
        float coef = __shfl_sync(0xffffffffu, cf, f4 >> 5);  // head = f4*4/128
        float4 hv = hsrc[f4];
        red4(dbase + f4 * 4, hv.x * coef, hv.y * coef, hv.z * coef, hv.w * coef);
    }
}

// ---------------- final: out = mean_heads(acc2) + res2 ---------------------------
__global__ void k_final(float* __restrict__ out, int N) {
    int i = blockIdx.x * blockDim.x + threadIdx.x;
    if (i >= N * 128) return;
    int n = i >> 7, c = i & 127;
    const float* a = &g_acc2[(size_t)n * 512 + c];
    out[i] = 0.25f * (a[0] + a[128] + a[256] + a[384]) + g_res[i];
}

// ---------------- host launch ----------------------------------------------------
extern "C" void kernel_launch(void* const* d_in, const int* in_sizes, int n_in,
                              void* d_out, int out_size) {
    const float* x      = (const float*)d_in[0];
    const int*   ei     = (const int*)  d_in[1];
    const int*   nt     = (const int*)  d_in[2];
    const float* ea     = (const float*)d_in[3];
    const int*   et     = (const int*)  d_in[4];
    const float* ne1    = (const float*)d_in[5];
    const float* w1     = (const float*)d_in[6];
    const float* we1    = (const float*)d_in[7];
    const float* asrc1  = (const float*)d_in[8];
    const float* adst1  = (const float*)d_in[9];
    const float* aedge1 = (const float*)d_in[10];
    const float* ee1    = (const float*)d_in[11];
    const float* wres1  = (const float*)d_in[12];
    const float* b1     = (const float*)d_in[13];
    const float* gamma  = (const float*)d_in[14];
    const float* beta   = (const float*)d_in[15];
    const float* ne2    = (const float*)d_in[16];
    const float* w2     = (const float*)d_in[17];
    const float* we2    = (const float*)d_in[18];
    const float* asrc2  = (const float*)d_in[19];
    const float* adst2  = (const float*)d_in[20];
    const float* aedge2 = (const float*)d_in[21];
    const float* ee2    = (const float*)d_in[22];
    const float* wres2  = (const float*)d_in[23];
    const float* b2     = (const float*)d_in[24];

    int N = in_sizes[0] / 32;
    int E = in_sizes[4];
    const int* src = ei;
    const int* dstp = ei + E;

    // ---- init + precompute ----
    k_init1<<<2048, 256>>>(N);
    k_pre_a<<<10, 256>>>(we1, aedge1, we2, aedge2, ne1, w1, ne2, w2);
    k_pre_b<<<1, 32>>>(ee1, ee2);

    // ---- layer 1 ----
    k_gemm1<<<(N + 63) / 64, 128>>>(x, nt, w1, wres1, b1, N);
    k_sd1<<<N, 128>>>(asrc1, adst1, N);
    k_edgeA1<<<(E + 7) / 8, 256>>>(src, dstp, ea, et, E);
    k_passB<<<(E * 4 + 255) / 256, 256>>>(dstp, E);
    k_aggr1<<<(E + 7) / 8, 256>>>(src, dstp, E);

    // ---- batch norm ----
    k_bnstats<<<296, 128>>>(N);
    k_bnfin<<<1, 128>>>(gamma, beta, N);

    // ---- layer 2 ----
    static int smem_set = 0;
    size_t smem = (64 * 132 + 128 * 128) * sizeof(float);  // 99328 B
    cudaFuncSetAttribute(k_gemm2, cudaFuncAttributeMaxDynamicSharedMemorySize, (int)smem);
    (void)smem_set;
    k_gemm2<<<(N + 63) / 64, 256, smem>>>(nt, w2, wres2, b2, N);
    k_sd2<<<N, 128>>>(asrc2, adst2, N);
    k_init2<<<256, 256>>>(N);
    k_edgeA2<<<(E * 4 + 255) / 256, 256>>>(src, dstp, E);
    k_passB<<<(E * 4 + 255) / 256, 256>>>(dstp, E);
    k_aggr2<<<(E + 7) / 8, 256>>>(src, dstp, E);

    // ---- epilogue ----
    k_final<<<(N * 128 + 255) / 256, 256>>>((float*)d_out, N);
}

// round 2
// speedup vs baseline: 1.1508x; 1.1508x over previous
#include <cuda_runtime.h>
#include <math.h>
#include <stdint.h>

// ---------------- problem-size bounds (N=50000, E=400000 in dataset) ----------
#define MAXN 50176
#define MAXE 400384

// ---------------- device scratch (no mallocs allowed) -------------------------
__device__ float  g_h1  [MAXN * 128];            // layer1 node embeddings [N,4,32]
__device__ float  g_res [MAXN * 128];            // residual (res1 then res2)
__device__ float  g_acc1[MAXN * 128];            // layer1 aggregate -> y -> BN input
__device__ float  g_h2  [(size_t)MAXN * 512];    // layer2 node embeddings [N,4,128]
__device__ float  g_acc2[MAXN * 128];            // layer2 head-averaged aggregate
__device__ float  g_s[MAXN * 4], g_d[MAXN * 4];  // attention src/dst terms
__device__ float  g_amax[MAXN * 4], g_den[MAXN * 4];
__device__ float  g_alpha[MAXE * 4];             // alpha, then exp(alpha-max)
__device__ float  g_e2[MAXE * 4];                // layer2 edge attention term
__device__ double g_colsum[128], g_colsq[128];
__device__ float  g_scale[128], g_shift[128];
__device__ float  g_aew1[64 * 4], g_aew2[64 * 4];
__device__ float  g_eea1[4 * 4],  g_eea2[4 * 4];
__device__ float  g_ne1w1[3 * 128], g_ne2w2[3 * 512];

// ---------------- helpers ------------------------------------------------------
__device__ __forceinline__ void atomicMaxF(float* a, float v) {
    unsigned int b = __float_as_uint(v);
    if (b >> 31) atomicMin((unsigned int*)a, b);   // negative: uint-min = float-max
    else         atomicMax((int*)a, (int)b);       // non-negative: int-max = float-max
}

__device__ __forceinline__ void red4(float* p, float a, float b, float c, float d) {
    asm volatile("red.global.add.v4.f32 [%0], {%1,%2,%3,%4};"
                 :: "l"(p), "f"(a), "f"(b), "f"(c), "f"(d) : "memory");
}

// Packed fp32x2 FMA (sm_100+): acc.lo += a.lo*b.lo; acc.hi += a.hi*b.hi (exact fp32)
__device__ __forceinline__ void ffma2(uint64_t& acc, uint64_t a, uint64_t b) {
    asm volatile("fma.rn.f32x2 %0, %1, %2, %0;" : "+l"(acc) : "l"(a), "l"(b));
}
__device__ __forceinline__ uint64_t pack2(float x, float y) {
    uint64_t r; asm("mov.b64 %0, {%1, %2};" : "=l"(r) : "f"(x), "f"(y)); return r;
}
__device__ __forceinline__ float2 unpack2(uint64_t v) {
    float2 r; asm("mov.b64 {%0, %1}, %2;" : "=f"(r.x), "=f"(r.y) : "l"(v)); return r;
}

// ---------------- init ----------------------------------------------------------
__global__ void k_init1(int N) {
    long i = (long)blockIdx.x * blockDim.x + threadIdx.x;
    long stride = (long)gridDim.x * blockDim.x;
    for (long j = i; j < (long)N * 128; j += stride) g_acc1[j] = 0.f;
    for (long j = i; j < (long)N * 4; j += stride) {
        g_den[j] = 0.f;
        g_amax[j] = __int_as_float(0xFF800000);  // -inf
    }
    if (i < 128) { g_colsum[i] = 0.0; g_colsq[i] = 0.0; }
}

__global__ void k_init2(int N) {
    long i = (long)blockIdx.x * blockDim.x + threadIdx.x;
    long stride = (long)gridDim.x * blockDim.x;
    for (long j = i; j < (long)N * 128; j += stride) g_acc2[j] = 0.f;
    for (long j = i; j < (long)N * 4; j += stride) {
        g_den[j] = 0.f;
        g_amax[j] = __int_as_float(0xFF800000);
    }
}

// ---------------- precompute: fold linear maps ----------------------------------
__global__ void k_pre_a(const float* __restrict__ we1, const float* __restrict__ aedge1,
                        const float* __restrict__ we2, const float* __restrict__ aedge2,
                        const float* __restrict__ ne1, const float* __restrict__ w1,
                        const float* __restrict__ ne2, const float* __restrict__ w2) {
    int i = blockIdx.x * blockDim.x + threadIdx.x;
    if (i < 256) {                       // aeW1: [64,4], C=32
        int k = i >> 2, h = i & 3; float a = 0.f;
        for (int c = 0; c < 32; c++) a += we1[k * 128 + h * 32 + c] * aedge1[h * 32 + c];
        g_aew1[i] = a;
    } else if (i < 512) {                // aeW2: [64,4], C=128
        int j = i - 256; int k = j >> 2, h = j & 3; float a = 0.f;
        for (int c = 0; c < 128; c++) a += we2[k * 512 + h * 128 + c] * aedge2[h * 128 + c];
        g_aew2[j] = a;
    } else if (i < 896) {                // ne1@w1: [3,128]
        int j = i - 512; int t = j >> 7, col = j & 127; float a = 0.f;
        for (int k = 0; k < 32; k++) a += ne1[t * 32 + k] * w1[k * 128 + col];
        g_ne1w1[j] = a;
    } else if (i < 2432) {               // ne2@w2: [3,512]
        int j = i - 896; int t = j >> 9, col = j & 511; float a = 0.f;
        for (int k = 0; k < 128; k++) a += ne2[t * 128 + k] * w2[k * 512 + col];
        g_ne2w2[j] = a;
    }
}

__global__ void k_pre_b(const float* __restrict__ ee1, const float* __restrict__ ee2) {
    int i = threadIdx.x;
    if (i < 16) {
        int t = i >> 2, h = i & 3; float a = 0.f;
        for (int k = 0; k < 64; k++) a += ee1[t * 64 + k] * g_aew1[k * 4 + h];
        g_eea1[i] = a;
    } else if (i < 32) {
        int j = i - 16; int t = j >> 2, h = j & 3; float a = 0.f;
        for (int k = 0; k < 64; k++) a += ee2[t * 64 + k] * g_aew2[k * 4 + h];
        g_eea2[j] = a;
    }
}

// ---------------- layer 1 GEMM (f32x2, k-paired, transposed-W smem) -------------
// h1 = x@w1 + (ne1@w1)[nt];  res1 = x@wres1 + b1
__global__ void k_gemm1(const float* __restrict__ x, const int* __restrict__ nt,
                        const float* __restrict__ w1, const float* __restrict__ wres1,
                        const float* __restrict__ b1, int N) {
    __shared__ __align__(16) float sWT[256 * 34];  // [c][k]: c<128 -> w1, else wres1
    __shared__ __align__(16) float sX[64 * 34];    // [r][k]
    int t = threadIdx.x;  // 128
    for (int i = t; i < 32 * 128; i += 128) {
        int k = i >> 7, c = i & 127;
        sWT[c * 34 + k]         = w1[i];
        sWT[(128 + c) * 34 + k] = wres1[i];
    }
    int r0 = blockIdx.x * 64;
    for (int i = t; i < 64 * 32; i += 128) {
        int r = i >> 5, k = i & 31; int gr = r0 + r;
        sX[r * 34 + k] = (gr < N) ? x[(size_t)gr * 32 + k] : 0.f;
    }
    __syncthreads();
    float bb = b1[t];
    const uint64_t* w1p = reinterpret_cast<const uint64_t*>(&sWT[t * 34]);
    const uint64_t* wrp = reinterpret_cast<const uint64_t*>(&sWT[(128 + t) * 34]);
    for (int rt = 0; rt < 8; rt++) {
        uint64_t a1[8], a2[8];
        #pragma unroll
        for (int j = 0; j < 8; j++) { a1[j] = 0ull; a2[j] = 0ull; }
        #pragma unroll
        for (int kp = 0; kp < 16; kp++) {
            uint64_t wv1 = w1p[kp], wv2 = wrp[kp];
            #pragma unroll
            for (int j = 0; j < 8; j++) {
                uint64_t x2 = *reinterpret_cast<const uint64_t*>(&sX[(rt * 8 + j) * 34 + kp * 2]);
                ffma2(a1[j], x2, wv1);
                ffma2(a2[j], x2, wv2);
            }
        }
        #pragma unroll
        for (int j = 0; j < 8; j++) {
            int gr = r0 + rt * 8 + j;
            if (gr < N) {
                float2 u = unpack2(a1[j]);
                float2 v = unpack2(a2[j]);
                g_h1 [(size_t)gr * 128 + t] = u.x + u.y + g_ne1w1[nt[gr] * 128 + t];
                g_res[(size_t)gr * 128 + t] = v.x + v.y + bb;
            }
        }
    }
}

// ---------------- s/d terms layer 1 ----------------------------------------------
__global__ void k_sd1(const float* __restrict__ asrc, const float* __restrict__ adst, int N) {
    int n = blockIdx.x; if (n >= N) return;
    int t = threadIdx.x;  // 128; t = h*32+c
    float h = g_h1[(size_t)n * 128 + t];
    float ps = h * asrc[t], pd = h * adst[t];
    for (int o = 16; o; o >>= 1) {
        ps += __shfl_xor_sync(0xffffffffu, ps, o);
        pd += __shfl_xor_sync(0xffffffffu, pd, o);
    }
    if ((t & 31) == 0) { int w = t >> 5; g_s[n * 4 + w] = ps; g_d[n * 4 + w] = pd; }
}

// ---------------- edge pass A (layer 1) -------------------------------------------
__global__ void k_edgeA1(const int* __restrict__ src, const int* __restrict__ dst,
                         const float* __restrict__ ea, const int* __restrict__ et, int E) {
    int e = blockIdx.x * 8 + (threadIdx.x >> 5); if (e >= E) return;
    int l = threadIdx.x & 31;
    float e1[4] = {0, 0, 0, 0}, e2[4] = {0, 0, 0, 0};
    const float* row = ea + (size_t)e * 64;
    for (int k = l; k < 64; k += 32) {
        float v = row[k];
        #pragma unroll
        for (int h = 0; h < 4; h++) { e1[h] += v * g_aew1[k * 4 + h]; e2[h] += v * g_aew2[k * 4 + h]; }
    }
    #pragma unroll
    for (int h = 0; h < 4; h++)
        for (int o = 16; o; o >>= 1) {
            e1[h] += __shfl_xor_sync(0xffffffffu, e1[h], o);
            e2[h] += __shfl_xor_sync(0xffffffffu, e2[h], o);
        }
    if (l < 4) {
        int s_ = src[e], d_ = dst[e], ty = et[e];
        float a = g_s[s_ * 4 + l] + g_d[d_ * 4 + l] + e1[l] + g_eea1[ty * 4 + l];
        a = (a >= 0.f) ? a : 0.2f * a;
        g_alpha[e * 4 + l] = a;
        atomicMaxF(&g_amax[d_ * 4 + l], a);
        g_e2[e * 4 + l] = e2[l] + g_eea2[ty * 4 + l];
    }
}

// ---------------- edge pass B (both layers) ---------------------------------------
__global__ void k_passB(const int* __restrict__ dst, int E) {
    int i = blockIdx.x * blockDim.x + threadIdx.x;
    if (i >= E * 4) return;
    int e = i >> 2, h = i & 3; int d_ = dst[e];
    float ex = expf(g_alpha[i] - g_amax[d_ * 4 + h]);
    g_alpha[i] = ex;
    atomicAdd(&g_den[d_ * 4 + h], ex);
}

// ---------------- edge aggregate layer 1 ------------------------------------------
__global__ void k_aggr1(const int* __restrict__ src, const int* __restrict__ dst, int E) {
    int e = blockIdx.x * 8 + (threadIdx.x >> 5); if (e >= E) return;
    int l = threadIdx.x & 31;
    int s_ = src[e], d_ = dst[e];
    float cf = 0.f;
    if (l < 4) cf = g_alpha[e * 4 + l] / (g_den[d_ * 4 + l] + 1e-16f);
    float coef = __shfl_sync(0xffffffffu, cf, l >> 3);  // head = (l*4)/32
    float4 hv = *reinterpret_cast<const float4*>(&g_h1[(size_t)s_ * 128 + l * 4]);
    red4(&g_acc1[(size_t)d_ * 128 + l * 4], hv.x * coef, hv.y * coef, hv.z * coef, hv.w * coef);
}

// ---------------- BN stats -----------------------------------------------------
__global__ void k_bnstats(int N) {
    int t = threadIdx.x;  // 128
    double s = 0.0, q = 0.0;
    for (int n = blockIdx.x; n < N; n += gridDim.x) {
        float y = g_acc1[(size_t)n * 128 + t] + g_res[(size_t)n * 128 + t];
        g_acc1[(size_t)n * 128 + t] = y;
        s += y; q += (double)y * y;
    }
    atomicAdd(&g_colsum[t], s);
    atomicAdd(&g_colsq[t], q);
}

__global__ void k_bnfin(const float* __restrict__ gamma, const float* __restrict__ beta, int N) {
    int t = threadIdx.x;
    double mu = g_colsum[t] / N;
    double var = g_colsq[t] / N - mu * mu;
    double sc = (double)gamma[t] / sqrt(var + 1e-5);
    g_scale[t] = (float)sc;
    g_shift[t] = (float)((double)beta[t] - mu * sc);
}

// ---------------- layer 2 GEMM (f32x2, col-paired) --------------------------------
// h2 = BN(y)@w2 + (ne2@w2)[nt];  res2 = BN(y)@wres2 + b2
__global__ void k_gemm2(const int* __restrict__ nt, const float* __restrict__ w2,
                        const float* __restrict__ wres2, const float* __restrict__ b2, int N) {
    extern __shared__ __align__(16) float sm[];
    float* sX = sm;               // 64 * 132
    float* sW = sm + 64 * 132;    // 128 * 128
    int t = threadIdx.x;          // 256
    int r0 = blockIdx.x * 64;
    for (int i = t; i < 64 * 128; i += 256) {
        int r = i >> 7, k = i & 127; int gr = r0 + r;
        float v = 0.f;
        if (gr < N) v = g_acc1[(size_t)gr * 128 + k] * g_scale[k] + g_shift[k];
        sX[r * 132 + k] = v;
    }
    int cg = t & 15, rg = t >> 4;
    int rbase = rg * 4, cbase = cg * 8;
    for (int ct = 0; ct < 5; ct++) {
        __syncthreads();
        for (int i = t; i < 128 * 128; i += 256) {
            int k = i >> 7, c = i & 127;
            sW[i] = (ct < 4) ? w2[(size_t)k * 512 + ct * 128 + c] : wres2[(size_t)k * 128 + c];
        }
        __syncthreads();
        uint64_t acc[4][4];
        #pragma unroll
        for (int j = 0; j < 4; j++)
            #pragma unroll
            for (int p = 0; p < 4; p++) acc[j][p] = 0ull;
        #pragma unroll 4
        for (int k = 0; k < 128; k++) {
            ulonglong2 wa = *reinterpret_cast<const ulonglong2*>(&sW[k * 128 + cbase]);
            ulonglong2 wb = *reinterpret_cast<const ulonglong2*>(&sW[k * 128 + cbase + 4]);
            #pragma unroll
            for (int j = 0; j < 4; j++) {
                float xv = sX[(rbase + j) * 132 + k];
                uint64_t x2 = pack2(xv, xv);
                ffma2(acc[j][0], x2, wa.x);
                ffma2(acc[j][1], x2, wa.y);
                ffma2(acc[j][2], x2, wb.x);
                ffma2(acc[j][3], x2, wb.y);
            }
        }
        #pragma unroll
        for (int j = 0; j < 4; j++) {
            int gr = r0 + rbase + j; if (gr >= N) continue;
            float o[8];
            #pragma unroll
            for (int p = 0; p < 4; p++) {
                float2 u = unpack2(acc[j][p]);
                o[2 * p] = u.x; o[2 * p + 1] = u.y;
            }
            if (ct < 4) {
                int ty = nt[gr];
                const float* bias = &g_ne2w2[ty * 512 + ct * 128 + cbase];
                float* dst = &g_h2[(size_t)gr * 512 + ct * 128 + cbase];
                *reinterpret_cast<float4*>(dst) =
                    make_float4(o[0] + bias[0], o[1] + bias[1], o[2] + bias[2], o[3] + bias[3]);
                *reinterpret_cast<float4*>(dst + 4) =
                    make_float4(o[4] + bias[4], o[5] + bias[5], o[6] + bias[6], o[7] + bias[7]);
            } else {
                const float* bias = &b2[cbase];
                float* dst = &g_res[(size_t)gr * 128 + cbase];
                *reinterpret_cast<float4*>(dst) =
                    make_float4(o[0] + bias[0], o[1] + bias[1], o[2] + bias[2], o[3] + bias[3]);
                *reinterpret_cast<float4*>(dst + 4) =
                    make_float4(o[4] + bias[4], o[5] + bias[5], o[6] + bias[6], o[7] + bias[7]);
            }
        }
    }
}

// ---------------- s/d terms layer 2 ------------------------------------------------
__global__ void k_sd2(const float* __restrict__ asrc, const float* __restrict__ adst, int N) {
    int n = blockIdx.x; if (n >= N) return;
    int t = threadIdx.x; int w = t >> 5, l = t & 31;
    float ps = 0.f, pd = 0.f;
    const float* hrow = &g_h2[(size_t)n * 512 + w * 128];
    const float* as = asrc + w * 128;
    const float* ad = adst + w * 128;
    for (int c = l; c < 128; c += 32) { float h = hrow[c]; ps += h * as[c]; pd += h * ad[c]; }
    for (int o = 16; o; o >>= 1) {
        ps += __shfl_xor_sync(0xffffffffu, ps, o);
        pd += __shfl_xor_sync(0xffffffffu, pd, o);
    }
    if (l == 0) { g_s[n * 4 + w] = ps; g_d[n * 4 + w] = pd; }
}

// ---------------- edge pass A (layer 2) --------------------------------------------
__global__ void k_edgeA2(const int* __restrict__ src, const int* __restrict__ dst, int E) {
    int i = blockIdx.x * blockDim.x + threadIdx.x;
    if (i >= E * 4) return;
    int e = i >> 2, h = i & 3;
    int s_ = src[e], d_ = dst[e];
    float a = g_s[s_ * 4 + h] + g_d[d_ * 4 + h] + g_e2[i];
    a = (a >= 0.f) ? a : 0.2f * a;
    g_alpha[i] = a;
    atomicMaxF(&g_amax[d_ * 4 + h], a);
}

// ---------------- edge aggregate layer 2 (head-mean fused) -------------------------
__global__ void k_aggr2(const int* __restrict__ src, const int* __restrict__ dst, int E) {
    int e = blockIdx.x * 8 + (threadIdx.x >> 5); if (e >= E) return;
    int l = threadIdx.x & 31;
    int s_ = src[e], d_ = dst[e];
    float cf = 0.f;
    if (l < 4) cf = 0.25f * g_alpha[e * 4 + l] / (g_den[d_ * 4 + l] + 1e-16f);
    float c0 = __shfl_sync(0xffffffffu, cf, 0);
    float c1 = __shfl_sync(0xffffffffu, cf, 1);
    float c2 = __shfl_sync(0xffffffffu, cf, 2);
    float c3 = __shfl_sync(0xffffffffu, cf, 3);
    const float4* hs = reinterpret_cast<const float4*>(&g_h2[(size_t)s_ * 512]);
    float4 h0 = hs[l], h1 = hs[32 + l], h2v = hs[64 + l], h3 = hs[96 + l];
    float mx = c0 * h0.x + c1 * h1.x + c2 * h2v.x + c3 * h3.x;
    float my = c0 * h0.y + c1 * h1.y + c2 * h2v.y + c3 * h3.y;
    float mz = c0 * h0.z + c1 * h1.z + c2 * h2v.z + c3 * h3.z;
    float mw = c0 * h0.w + c1 * h1.w + c2 * h2v.w + c3 * h3.w;
    red4(&g_acc2[(size_t)d_ * 128 + l * 4], mx, my, mz, mw);
}

// ---------------- final: out = acc2 (head-mean already folded) + res2 ---------------
__global__ void k_final(float4* __restrict__ out, int N) {
    int i = blockIdx.x * blockDim.x + threadIdx.x;
    if (i >= N * 32) return;
    const float4 a = reinterpret_cast<const float4*>(g_acc2)[i];
    const float4 r = reinterpret_cast<const float4*>(g_res)[i];
    out[i] = make_float4(a.x + r.x, a.y + r.y, a.z + r.z, a.w + r.w);
}

// ---------------- host launch ----------------------------------------------------
extern "C" void kernel_launch(void* const* d_in, const int* in_sizes, int n_in,
                              void* d_out, int out_size) {
    const float* x      = (const float*)d_in[0];
    const int*   ei     = (const int*)  d_in[1];
    const int*   nt     = (const int*)  d_in[2];
    const float* ea     = (const float*)d_in[3];
    const int*   et     = (const int*)  d_in[4];
    const float* ne1    = (const float*)d_in[5];
    const float* w1     = (const float*)d_in[6];
    const float* we1    = (const float*)d_in[7];
    const float* asrc1  = (const float*)d_in[8];
    const float* adst1  = (const float*)d_in[9];
    const float* aedge1 = (const float*)d_in[10];
    const float* ee1    = (const float*)d_in[11];
    const float* wres1  = (const float*)d_in[12];
    const float* b1     = (const float*)d_in[13];
    const float* gamma  = (const float*)d_in[14];
    const float* beta   = (const float*)d_in[15];
    const float* ne2    = (const float*)d_in[16];
    const float* w2     = (const float*)d_in[17];
    const float* we2    = (const float*)d_in[18];
    const float* asrc2  = (const float*)d_in[19];
    const float* adst2  = (const float*)d_in[20];
    const float* aedge2 = (const float*)d_in[21];
    const float* ee2    = (const float*)d_in[22];
    const float* wres2  = (const float*)d_in[23];
    const float* b2     = (const float*)d_in[24];

    int N = in_sizes[0] / 32;
    int E = in_sizes[4];
    const int* src = ei;
    const int* dstp = ei + E;

    // ---- init + precompute ----
    k_init1<<<1024, 256>>>(N);
    k_pre_a<<<10, 256>>>(we1, aedge1, we2, aedge2, ne1, w1, ne2, w2);
    k_pre_b<<<1, 32>>>(ee1, ee2);

    // ---- layer 1 ----
    k_gemm1<<<(N + 63) / 64, 128>>>(x, nt, w1, wres1, b1, N);
    k_sd1<<<N, 128>>>(asrc1, adst1, N);
    k_edgeA1<<<(E + 7) / 8, 256>>>(src, dstp, ea, et, E);
    k_passB<<<(E * 4 + 255) / 256, 256>>>(dstp, E);
    k_aggr1<<<(E + 7) / 8, 256>>>(src, dstp, E);

    // ---- batch norm ----
    k_bnstats<<<296, 128>>>(N);
    k_bnfin<<<1, 128>>>(gamma, beta, N);

    // ---- layer 2 ----
    size_t smem = (64 * 132 + 128 * 128) * sizeof(float);  // 99328 B
    cudaFuncSetAttribute(k_gemm2, cudaFuncAttributeMaxDynamicSharedMemorySize, (int)smem);
    k_gemm2<<<(N + 63) / 64, 256, smem>>>(nt, w2, wres2, b2, N);
    k_sd2<<<N, 128>>>(asrc2, adst2, N);
    k_init2<<<1024, 256>>>(N);
    k_edgeA2<<<(E * 4 + 255) / 256, 256>>>(src, dstp, E);
    k_passB<<<(E * 4 + 255) / 256, 256>>>(dstp, E);
    k_aggr2<<<(E + 7) / 8, 256>>>(src, dstp, E);

    // ---- epilogue ----
    k_final<<<(N * 32 + 255) / 256, 256>>>((float4*)d_out, N);
}

// round 3
// speedup vs baseline: 1.4731x; 1.2800x over previous
#include <cuda_runtime.h>
#include <math.h>
#include <stdint.h>

// ---------------- problem-size bounds (N=50000, E=400000 in dataset) ----------
#define MAXN 50176
#define MAXE 400384

// ---------------- device scratch (no mallocs allowed) -------------------------
__device__ float  g_h1  [MAXN * 128];            // layer1 node embeddings [N,4,32]
__device__ float  g_res [MAXN * 128];            // residual (res1 then res2)
__device__ float  g_acc1[MAXN * 128];            // layer1 aggregate -> y -> BN input
__device__ float  g_h2  [(size_t)MAXN * 512];    // layer2 node embeddings [N,4,128]
__device__ float  g_acc2[MAXN * 128];            // layer2 head-averaged aggregate
__device__ float  g_s[MAXN * 4], g_d[MAXN * 4];  // attention src/dst terms
__device__ float  g_amax[MAXN * 4], g_den[MAXN * 4];
__device__ float  g_alpha[MAXE * 4];             // alpha, then exp(alpha-max)
__device__ float  g_e2[MAXE * 4];                // layer2 edge attention term
__device__ double g_colsum[128], g_colsq[128];
__device__ float  g_scale[128], g_shift[128];
__device__ float  g_aew1[64 * 4], g_aew2[64 * 4];
__device__ float  g_eea1[4 * 4],  g_eea2[4 * 4];
__device__ float  g_ne1w1[3 * 128], g_ne2w2[3 * 512];

// ---------------- helpers ------------------------------------------------------
__device__ __forceinline__ void atomicMaxF(float* a, float v) {
    unsigned int b = __float_as_uint(v);
    if (b >> 31) atomicMin((unsigned int*)a, b);   // negative: uint-min = float-max
    else         atomicMax((int*)a, (int)b);       // non-negative: int-max = float-max
}

__device__ __forceinline__ void red4(float* p, float a, float b, float c, float d) {
    asm volatile("red.global.add.v4.f32 [%0], {%1,%2,%3,%4};"
                 :: "l"(p), "f"(a), "f"(b), "f"(c), "f"(d) : "memory");
}

// Packed fp32x2 FMA (sm_100+): acc.lo += a.lo*b.lo; acc.hi += a.hi*b.hi (exact fp32)
__device__ __forceinline__ void ffma2(uint64_t& acc, uint64_t a, uint64_t b) {
    asm volatile("fma.rn.f32x2 %0, %1, %2, %0;" : "+l"(acc) : "l"(a), "l"(b));
}
__device__ __forceinline__ uint64_t pack2(float x, float y) {
    uint64_t r; asm("mov.b64 %0, {%1, %2};" : "=l"(r) : "f"(x), "f"(y)); return r;
}
__device__ __forceinline__ float2 unpack2(uint64_t v) {
    float2 r; asm("mov.b64 {%0, %1}, %2;" : "=f"(r.x), "=f"(r.y) : "l"(v)); return r;
}

// ---------------- init ----------------------------------------------------------
__global__ void k_init1(int N) {
    long i = (long)blockIdx.x * blockDim.x + threadIdx.x;
    long stride = (long)gridDim.x * blockDim.x;
    for (long j = i; j < (long)N * 128; j += stride) g_acc1[j] = 0.f;
    for (long j = i; j < (long)N * 4; j += stride) {
        g_den[j] = 0.f;
        g_amax[j] = __int_as_float(0xFF800000);  // -inf
    }
    if (i < 128) { g_colsum[i] = 0.0; g_colsq[i] = 0.0; }
}

__global__ void k_init2(int N) {
    long i = (long)blockIdx.x * blockDim.x + threadIdx.x;
    long stride = (long)gridDim.x * blockDim.x;
    for (long j = i; j < (long)N * 128; j += stride) g_acc2[j] = 0.f;
    for (long j = i; j < (long)N * 4; j += stride) {
        g_den[j] = 0.f;
        g_amax[j] = __int_as_float(0xFF800000);
    }
}

// ---------------- precompute: fold linear maps ----------------------------------
__global__ void k_pre_a(const float* __restrict__ we1, const float* __restrict__ aedge1,
                        const float* __restrict__ we2, const float* __restrict__ aedge2,
                        const float* __restrict__ ne1, const float* __restrict__ w1,
                        const float* __restrict__ ne2, const float* __restrict__ w2) {
    int i = blockIdx.x * blockDim.x + threadIdx.x;
    if (i < 256) {                       // aeW1: [64,4], C=32
        int k = i >> 2, h = i & 3; float a = 0.f;
        for (int c = 0; c < 32; c++) a += we1[k * 128 + h * 32 + c] * aedge1[h * 32 + c];
        g_aew1[i] = a;
    } else if (i < 512) {                // aeW2: [64,4], C=128
        int j = i - 256; int k = j >> 2, h = j & 3; float a = 0.f;
        for (int c = 0; c < 128; c++) a += we2[k * 512 + h * 128 + c] * aedge2[h * 128 + c];
        g_aew2[j] = a;
    } else if (i < 896) {                // ne1@w1: [3,128]
        int j = i - 512; int t = j >> 7, col = j & 127; float a = 0.f;
        for (int k = 0; k < 32; k++) a += ne1[t * 32 + k] * w1[k * 128 + col];
        g_ne1w1[j] = a;
    } else if (i < 2432) {               // ne2@w2: [3,512]
        int j = i - 896; int t = j >> 9, col = j & 511; float a = 0.f;
        for (int k = 0; k < 128; k++) a += ne2[t * 128 + k] * w2[k * 512 + col];
        g_ne2w2[j] = a;
    }
}

__global__ void k_pre_b(const float* __restrict__ ee1, const float* __restrict__ ee2) {
    int i = threadIdx.x;
    if (i < 16) {
        int t = i >> 2, h = i & 3; float a = 0.f;
        for (int k = 0; k < 64; k++) a += ee1[t * 64 + k] * g_aew1[k * 4 + h];
        g_eea1[i] = a;
    } else if (i < 32) {
        int j = i - 16; int t = j >> 2, h = j & 3; float a = 0.f;
        for (int k = 0; k < 64; k++) a += ee2[t * 64 + k] * g_aew2[k * 4 + h];
        g_eea2[j] = a;
    }
}

// ---------------- layer 1 GEMM (f32x2, k-paired, transposed-W smem) -------------
__global__ void k_gemm1(const float* __restrict__ x, const int* __restrict__ nt,
                        const float* __restrict__ w1, const float* __restrict__ wres1,
                        const float* __restrict__ b1, int N) {
    __shared__ __align__(16) float sWT[256 * 34];  // [c][k]: c<128 -> w1, else wres1
    __shared__ __align__(16) float sX[64 * 34];    // [r][k]
    int t = threadIdx.x;  // 128
    for (int i = t; i < 32 * 128; i += 128) {
        int k = i >> 7, c = i & 127;
        sWT[c * 34 + k]         = w1[i];
        sWT[(128 + c) * 34 + k] = wres1[i];
    }
    int r0 = blockIdx.x * 64;
    for (int i = t; i < 64 * 32; i += 128) {
        int r = i >> 5, k = i & 31; int gr = r0 + r;
        sX[r * 34 + k] = (gr < N) ? x[(size_t)gr * 32 + k] : 0.f;
    }
    __syncthreads();
    float bb = b1[t];
    const uint64_t* w1p = reinterpret_cast<const uint64_t*>(&sWT[t * 34]);
    const uint64_t* wrp = reinterpret_cast<const uint64_t*>(&sWT[(128 + t) * 34]);
    for (int rt = 0; rt < 8; rt++) {
        uint64_t a1[8], a2[8];
        #pragma unroll
        for (int j = 0; j < 8; j++) { a1[j] = 0ull; a2[j] = 0ull; }
        #pragma unroll
        for (int kp = 0; kp < 16; kp++) {
            uint64_t wv1 = w1p[kp], wv2 = wrp[kp];
            #pragma unroll
            for (int j = 0; j < 8; j++) {
                uint64_t x2 = *reinterpret_cast<const uint64_t*>(&sX[(rt * 8 + j) * 34 + kp * 2]);
                ffma2(a1[j], x2, wv1);
                ffma2(a2[j], x2, wv2);
            }
        }
        #pragma unroll
        for (int j = 0; j < 8; j++) {
            int gr = r0 + rt * 8 + j;
            if (gr < N) {
                float2 u = unpack2(a1[j]);
                float2 v = unpack2(a2[j]);
                g_h1 [(size_t)gr * 128 + t] = u.x + u.y + g_ne1w1[nt[gr] * 128 + t];
                g_res[(size_t)gr * 128 + t] = v.x + v.y + bb;
            }
        }
    }
}

// ---------------- s/d terms layer 1 ----------------------------------------------
__global__ void k_sd1(const float* __restrict__ asrc, const float* __restrict__ adst, int N) {
    int n = blockIdx.x; if (n >= N) return;
    int t = threadIdx.x;  // 128; t = h*32+c
    float h = g_h1[(size_t)n * 128 + t];
    float ps = h * asrc[t], pd = h * adst[t];
    for (int o = 16; o; o >>= 1) {
        ps += __shfl_xor_sync(0xffffffffu, ps, o);
        pd += __shfl_xor_sync(0xffffffffu, pd, o);
    }
    if ((t & 31) == 0) { int w = t >> 5; g_s[n * 4 + w] = ps; g_d[n * 4 + w] = pd; }
}

// ---------------- edge pass A (layer 1) -------------------------------------------
__global__ void k_edgeA1(const int* __restrict__ src, const int* __restrict__ dst,
                         const float* __restrict__ ea, const int* __restrict__ et, int E) {
    int e = blockIdx.x * 8 + (threadIdx.x >> 5); if (e >= E) return;
    int l = threadIdx.x & 31;
    float e1[4] = {0, 0, 0, 0}, e2[4] = {0, 0, 0, 0};
    const float* row = ea + (size_t)e * 64;
    for (int k = l; k < 64; k += 32) {
        float v = row[k];
        #pragma unroll
        for (int h = 0; h < 4; h++) { e1[h] += v * g_aew1[k * 4 + h]; e2[h] += v * g_aew2[k * 4 + h]; }
    }
    #pragma unroll
    for (int h = 0; h < 4; h++)
        for (int o = 16; o; o >>= 1) {
            e1[h] += __shfl_xor_sync(0xffffffffu, e1[h], o);
            e2[h] += __shfl_xor_sync(0xffffffffu, e2[h], o);
        }
    if (l < 4) {
        int s_ = src[e], d_ = dst[e], ty = et[e];
        float a = g_s[s_ * 4 + l] + g_d[d_ * 4 + l] + e1[l] + g_eea1[ty * 4 + l];
        a = (a >= 0.f) ? a : 0.2f * a;
        g_alpha[e * 4 + l] = a;
        atomicMaxF(&g_amax[d_ * 4 + l], a);
        g_e2[e * 4 + l] = e2[l] + g_eea2[ty * 4 + l];
    }
}

// ---------------- edge pass B (both layers) ---------------------------------------
__global__ void k_passB(const int* __restrict__ dst, int E) {
    int i = blockIdx.x * blockDim.x + threadIdx.x;
    if (i >= E * 4) return;
    int e = i >> 2, h = i & 3; int d_ = dst[e];
    float ex = __expf(g_alpha[i] - g_amax[d_ * 4 + h]);
    g_alpha[i] = ex;
    atomicAdd(&g_den[d_ * 4 + h], ex);
}

// ---------------- edge aggregate layer 1 ------------------------------------------
__global__ void k_aggr1(const int* __restrict__ src, const int* __restrict__ dst, int E) {
    int e = blockIdx.x * 8 + (threadIdx.x >> 5); if (e >= E) return;
    int l = threadIdx.x & 31;
    int s_ = src[e], d_ = dst[e];
    float cf = 0.f;
    if (l < 4) cf = g_alpha[e * 4 + l] / (g_den[d_ * 4 + l] + 1e-16f);
    float coef = __shfl_sync(0xffffffffu, cf, l >> 3);  // head = (l*4)/32
    float4 hv = *reinterpret_cast<const float4*>(&g_h1[(size_t)s_ * 128 + l * 4]);
    red4(&g_acc1[(size_t)d_ * 128 + l * 4], hv.x * coef, hv.y * coef, hv.z * coef, hv.w * coef);
}

// ---------------- BN stats -----------------------------------------------------
__global__ void k_bnstats(int N) {
    int t = threadIdx.x;  // 128
    double s = 0.0, q = 0.0;
    for (int n = blockIdx.x; n < N; n += gridDim.x) {
        float y = g_acc1[(size_t)n * 128 + t] + g_res[(size_t)n * 128 + t];
        g_acc1[(size_t)n * 128 + t] = y;
        s += y; q += (double)y * y;
    }
    atomicAdd(&g_colsum[t], s);
    atomicAdd(&g_colsq[t], q);
}

__global__ void k_bnfin(const float* __restrict__ gamma, const float* __restrict__ beta, int N) {
    int t = threadIdx.x;
    double mu = g_colsum[t] / N;
    double var = g_colsq[t] / N - mu * mu;
    double sc = (double)gamma[t] / sqrt(var + 1e-5);
    g_scale[t] = (float)sc;
    g_shift[t] = (float)((double)beta[t] - mu * sc);
}

// ---------------- layer 2 GEMM v2: 128x128 tile, 8x8/thread, f32x2 ----------------
// h2 = BN(y)@w2 + (ne2@w2)[nt]; res2 = BN(y)@wres2 + b2; fused s/d dot products.
__global__ void __launch_bounds__(256, 2)
k_gemm2(const int* __restrict__ nt, const float* __restrict__ w2,
        const float* __restrict__ wres2, const float* __restrict__ b2,
        const float* __restrict__ asrc, const float* __restrict__ adst, int N) {
    extern __shared__ __align__(16) float sm[];
    float* sXT = sm;               // [k:128][r:132 pad]  (BN applied)
    float* sW  = sm + 128 * 132;   // [k:64][c:132 pad]
    int t = threadIdx.x;           // 256
    int r0 = blockIdx.x * 128;
    int tc = t & 15, tr = t >> 4;  // 16x16 thread grid: 8 cols x 8 rows each

    // stage X (transposed, BN folded)
    for (int i = t; i < 128 * 128; i += 256) {
        int r = i >> 7, k = i & 127; int gr = r0 + r;
        float v = 0.f;
        if (gr < N) v = g_acc1[(size_t)gr * 128 + k] * g_scale[k] + g_shift[k];
        sXT[k * 132 + r] = v;
    }

    for (int ct = 0; ct < 5; ct++) {
        uint64_t acc[8][4];
        #pragma unroll
        for (int j = 0; j < 8; j++)
            #pragma unroll
            for (int p = 0; p < 4; p++) acc[j][p] = 0ull;

        for (int kh = 0; kh < 2; kh++) {
            __syncthreads();
            // stage W half-tile [64 k][128 c]
            for (int i = t; i < 64 * 32; i += 256) {
                int k = i >> 5, c4 = i & 31;
                float4 wv;
                if (ct < 4) wv = *reinterpret_cast<const float4*>(
                                 &w2[(size_t)(kh * 64 + k) * 512 + ct * 128 + c4 * 4]);
                else        wv = *reinterpret_cast<const float4*>(
                                 &wres2[(size_t)(kh * 64 + k) * 128 + c4 * 4]);
                *reinterpret_cast<float4*>(&sW[k * 132 + c4 * 4]) = wv;
            }
            __syncthreads();

            const float* xbase = sXT + kh * 64 * 132 + tr * 8;
            const float* wbase = sW + tc * 8;
            #pragma unroll 4
            for (int k = 0; k < 64; k++) {
                float4 xa = *reinterpret_cast<const float4*>(xbase + k * 132);
                float4 xb = *reinterpret_cast<const float4*>(xbase + k * 132 + 4);
                ulonglong2 wa = *reinterpret_cast<const ulonglong2*>(wbase + k * 132);
                ulonglong2 wb = *reinterpret_cast<const ulonglong2*>(wbase + k * 132 + 4);
                float xs[8] = {xa.x, xa.y, xa.z, xa.w, xb.x, xb.y, xb.z, xb.w};
                #pragma unroll
                for (int j = 0; j < 8; j++) {
                    uint64_t x2 = pack2(xs[j], xs[j]);
                    ffma2(acc[j][0], x2, wa.x);
                    ffma2(acc[j][1], x2, wa.y);
                    ffma2(acc[j][2], x2, wb.x);
                    ffma2(acc[j][3], x2, wb.y);
                }
            }
        }

        // epilogue
        if (ct < 4) {
            float av[8], dv[8];
            #pragma unroll
            for (int i = 0; i < 8; i++) {
                av[i] = asrc[ct * 128 + tc * 8 + i];
                dv[i] = adst[ct * 128 + tc * 8 + i];
            }
            #pragma unroll
            for (int j = 0; j < 8; j++) {
                int gr = r0 + tr * 8 + j;
                float o[8];
                #pragma unroll
                for (int p = 0; p < 4; p++) {
                    float2 u = unpack2(acc[j][p]);
                    o[2 * p] = u.x; o[2 * p + 1] = u.y;
                }
                int ty = (gr < N) ? nt[gr] : 0;
                const float* bias = &g_ne2w2[ty * 512 + ct * 128 + tc * 8];
                float sp = 0.f, dp = 0.f;
                #pragma unroll
                for (int i = 0; i < 8; i++) {
                    o[i] += bias[i];
                    sp += o[i] * av[i];
                    dp += o[i] * dv[i];
                }
                #pragma unroll
                for (int off = 8; off; off >>= 1) {
                    sp += __shfl_xor_sync(0xffffffffu, sp, off);
                    dp += __shfl_xor_sync(0xffffffffu, dp, off);
                }
                if (gr < N) {
                    float* dst = &g_h2[(size_t)gr * 512 + ct * 128 + tc * 8];
                    *reinterpret_cast<float4*>(dst)     = make_float4(o[0], o[1], o[2], o[3]);
                    *reinterpret_cast<float4*>(dst + 4) = make_float4(o[4], o[5], o[6], o[7]);
                    if (tc == 0) { g_s[gr * 4 + ct] = sp; g_d[gr * 4 + ct] = dp; }
                }
            }
        } else {
            #pragma unroll
            for (int j = 0; j < 8; j++) {
                int gr = r0 + tr * 8 + j; if (gr >= N) continue;
                float o[8];
                #pragma unroll
                for (int p = 0; p < 4; p++) {
                    float2 u = unpack2(acc[j][p]);
                    o[2 * p] = u.x; o[2 * p + 1] = u.y;
                }
                const float* bias = &b2[tc * 8];
                float* dst = &g_res[(size_t)gr * 128 + tc * 8];
                *reinterpret_cast<float4*>(dst) =
                    make_float4(o[0] + bias[0], o[1] + bias[1], o[2] + bias[2], o[3] + bias[3]);
                *reinterpret_cast<float4*>(dst + 4) =
                    make_float4(o[4] + bias[4], o[5] + bias[5], o[6] + bias[6], o[7] + bias[7]);
            }
        }
    }
}

// ---------------- edge pass A (layer 2) --------------------------------------------
__global__ void k_edgeA2(const int* __restrict__ src, const int* __restrict__ dst, int E) {
    int i = blockIdx.x * blockDim.x + threadIdx.x;
    if (i >= E * 4) return;
    int e = i >> 2, h = i & 3;
    int s_ = src[e], d_ = dst[e];
    float a = g_s[s_ * 4 + h] + g_d[d_ * 4 + h] + g_e2[i];
    a = (a >= 0.f) ? a : 0.2f * a;
    g_alpha[i] = a;
    atomicMaxF(&g_amax[d_ * 4 + h], a);
}

// ---------------- edge aggregate layer 2 (head-mean fused) -------------------------
__global__ void k_aggr2(const int* __restrict__ src, const int* __restrict__ dst, int E) {
    int e = blockIdx.x * 8 + (threadIdx.x >> 5); if (e >= E) return;
    int l = threadIdx.x & 31;
    int s_ = src[e], d_ = dst[e];
    float cf = 0.f;
    if (l < 4) cf = 0.25f * g_alpha[e * 4 + l] / (g_den[d_ * 4 + l] + 1e-16f);
    float c0 = __shfl_sync(0xffffffffu, cf, 0);
    float c1 = __shfl_sync(0xffffffffu, cf, 1);
    float c2 = __shfl_sync(0xffffffffu, cf, 2);
    float c3 = __shfl_sync(0xffffffffu, cf, 3);
    const float4* hs = reinterpret_cast<const float4*>(&g_h2[(size_t)s_ * 512]);
    float4 h0 = hs[l], h1 = hs[32 + l], h2v = hs[64 + l], h3 = hs[96 + l];
    float mx = c0 * h0.x + c1 * h1.x + c2 * h2v.x + c3 * h3.x;
    float my = c0 * h0.y + c1 * h1.y + c2 * h2v.y + c3 * h3.y;
    float mz = c0 * h0.z + c1 * h1.z + c2 * h2v.z + c3 * h3.z;
    float mw = c0 * h0.w + c1 * h1.w + c2 * h2v.w + c3 * h3.w;
    red4(&g_acc2[(size_t)d_ * 128 + l * 4], mx, my, mz, mw);
}

// ---------------- final: out = acc2 + res2 -----------------------------------------
__global__ void k_final(float4* __restrict__ out, int N) {
    int i = blockIdx.x * blockDim.x + threadIdx.x;
    if (i >= N * 32) return;
    const float4 a = reinterpret_cast<const float4*>(g_acc2)[i];
    const float4 r = reinterpret_cast<const float4*>(g_res)[i];
    out[i] = make_float4(a.x + r.x, a.y + r.y, a.z + r.z, a.w + r.w);
}

// ---------------- host launch ----------------------------------------------------
extern "C" void kernel_launch(void* const* d_in, const int* in_sizes, int n_in,
                              void* d_out, int out_size) {
    const float* x      = (const float*)d_in[0];
    const int*   ei     = (const int*)  d_in[1];
    const int*   nt     = (const int*)  d_in[2];
    const float* ea     = (const float*)d_in[3];
    const int*   et     = (const int*)  d_in[4];
    const float* ne1    = (const float*)d_in[5];
    const float* w1     = (const float*)d_in[6];
    const float* we1    = (const float*)d_in[7];
    const float* asrc1  = (const float*)d_in[8];
    const float* adst1  = (const float*)d_in[9];
    const float* aedge1 = (const float*)d_in[10];
    const float* ee1    = (const float*)d_in[11];
    const float* wres1  = (const float*)d_in[12];
    const float* b1     = (const float*)d_in[13];
    const float* gamma  = (const float*)d_in[14];
    const float* beta   = (const float*)d_in[15];
    const float* ne2    = (const float*)d_in[16];
    const float* w2     = (const float*)d_in[17];
    const float* we2    = (const float*)d_in[18];
    const float* asrc2  = (const float*)d_in[19];
    const float* adst2  = (const float*)d_in[20];
    const float* aedge2 = (const float*)d_in[21];
    const float* ee2    = (const float*)d_in[22];
    const float* wres2  = (const float*)d_in[23];
    const float* b2     = (const float*)d_in[24];

    int N = in_sizes[0] / 32;
    int E = in_sizes[4];
    const int* src = ei;
    const int* dstp = ei + E;

    // ---- init + precompute ----
    k_init1<<<1024, 256>>>(N);
    k_pre_a<<<10, 256>>>(we1, aedge1, we2, aedge2, ne1, w1, ne2, w2);
    k_pre_b<<<1, 32>>>(ee1, ee2);

    // ---- layer 1 ----
    k_gemm1<<<(N + 63) / 64, 128>>>(x, nt, w1, wres1, b1, N);
    k_sd1<<<N, 128>>>(asrc1, adst1, N);
    k_edgeA1<<<(E + 7) / 8, 256>>>(src, dstp, ea, et, E);
    k_passB<<<(E * 4 + 255) / 256, 256>>>(dstp, E);
    k_aggr1<<<(E + 7) / 8, 256>>>(src, dstp, E);

    // ---- batch norm ----
    k_bnstats<<<296, 128>>>(N);
    k_bnfin<<<1, 128>>>(gamma, beta, N);

    // ---- layer 2 ----
    size_t smem = (128 * 132 + 64 * 132) * sizeof(float);  // 101376 B
    cudaFuncSetAttribute(k_gemm2, cudaFuncAttributeMaxDynamicSharedMemorySize, (int)smem);
    k_gemm2<<<(N + 127) / 128, 256, smem>>>(nt, w2, wres2, b2, asrc2, adst2, N);
    k_init2<<<1024, 256>>>(N);
    k_edgeA2<<<(E * 4 + 255) / 256, 256>>>(src, dstp, E);
    k_passB<<<(E * 4 + 255) / 256, 256>>>(dstp, E);
    k_aggr2<<<(E + 7) / 8, 256>>>(src, dstp, E);

    // ---- epilogue ----
    k_final<<<(N * 32 + 255) / 256, 256>>>((float4*)d_out, N);
}

// round 4
// speedup vs baseline: 1.8376x; 1.2474x over previous
#include <cuda_runtime.h>
#include <math.h>
#include <stdint.h>

// ---------------- problem-size bounds (N=50000, E=400000 in dataset) ----------
#define MAXN 50176
#define MAXE 400384

// ---------------- device scratch (no mallocs allowed) -------------------------
__device__ float  g_h1  [MAXN * 128];            // layer1 node embeddings [N,4,32]
__device__ float  g_res [MAXN * 128];            // residual (res1 then res2)
__device__ float  g_acc1[MAXN * 128];            // layer1 aggregate -> y -> BN input
__device__ float  g_h2  [(size_t)MAXN * 512];    // layer2 node embeddings [N,4,128]
__device__ float  g_acc2[MAXN * 128];            // layer2 head-averaged aggregate
__device__ float  g_s[MAXN * 4], g_d[MAXN * 4];  // attention src/dst terms
__device__ float  g_amax[MAXN * 4], g_den[MAXN * 4];
__device__ float  g_alpha[MAXE * 4];             // alpha, then exp(alpha-max)
__device__ float  g_e2[MAXE * 4];                // layer2 edge attention term
__device__ double g_colsum[128], g_colsq[128];
__device__ float  g_scale[128], g_shift[128];
__device__ float  g_aew1T[4 * 64], g_aew2T[4 * 64];  // transposed [h][k]
__device__ float  g_eea1[4 * 4],  g_eea2[4 * 4];
__device__ float  g_ne1w1[3 * 128], g_ne2w2[3 * 512];

// ---------------- helpers ------------------------------------------------------
__device__ __forceinline__ void atomicMaxF(float* a, float v) {
    unsigned int b = __float_as_uint(v);
    if (b >> 31) atomicMin((unsigned int*)a, b);   // negative: uint-min = float-max
    else         atomicMax((int*)a, (int)b);       // non-negative: int-max = float-max
}

__device__ __forceinline__ void red4(float* p, float a, float b, float c, float d) {
    asm volatile("red.global.add.v4.f32 [%0], {%1,%2,%3,%4};"
                 :: "l"(p), "f"(a), "f"(b), "f"(c), "f"(d) : "memory");
}

// Packed fp32x2 FMA (sm_100+): acc.lo += a.lo*b.lo; acc.hi += a.hi*b.hi (exact fp32)
__device__ __forceinline__ void ffma2(uint64_t& acc, uint64_t a, uint64_t b) {
    asm volatile("fma.rn.f32x2 %0, %1, %2, %0;" : "+l"(acc) : "l"(a), "l"(b));
}
__device__ __forceinline__ uint64_t pack2(float x, float y) {
    uint64_t r; asm("mov.b64 %0, {%1, %2};" : "=l"(r) : "f"(x), "f"(y)); return r;
}
__device__ __forceinline__ float2 unpack2(uint64_t v) {
    float2 r; asm("mov.b64 {%0, %1}, %2;" : "=f"(r.x), "=f"(r.y) : "l"(v)); return r;
}

// ---------------- init ----------------------------------------------------------
__global__ void k_init1(int N) {
    long i = (long)blockIdx.x * blockDim.x + threadIdx.x;
    long stride = (long)gridDim.x * blockDim.x;
    for (long j = i; j < (long)N * 128; j += stride) g_acc1[j] = 0.f;
    for (long j = i; j < (long)N * 4; j += stride) {
        g_den[j] = 0.f;
        g_amax[j] = __int_as_float(0xFF800000);  // -inf
    }
    if (i < 128) { g_colsum[i] = 0.0; g_colsq[i] = 0.0; }
}

__global__ void k_init2(int N) {
    long i = (long)blockIdx.x * blockDim.x + threadIdx.x;
    long stride = (long)gridDim.x * blockDim.x;
    for (long j = i; j < (long)N * 128; j += stride) g_acc2[j] = 0.f;
    for (long j = i; j < (long)N * 4; j += stride) {
        g_den[j] = 0.f;
        g_amax[j] = __int_as_float(0xFF800000);
    }
}

// ---------------- precompute: fold linear maps ----------------------------------
__global__ void k_pre_a(const float* __restrict__ we1, const float* __restrict__ aedge1,
                        const float* __restrict__ we2, const float* __restrict__ aedge2,
                        const float* __restrict__ ne1, const float* __restrict__ w1,
                        const float* __restrict__ ne2, const float* __restrict__ w2) {
    int i = blockIdx.x * blockDim.x + threadIdx.x;
    if (i < 256) {                       // aeW1^T: [4][64], C=32
        int k = i >> 2, h = i & 3; float a = 0.f;
        for (int c = 0; c < 32; c++) a += we1[k * 128 + h * 32 + c] * aedge1[h * 32 + c];
        g_aew1T[h * 64 + k] = a;
    } else if (i < 512) {                // aeW2^T: [4][64], C=128
        int j = i - 256; int k = j >> 2, h = j & 3; float a = 0.f;
        for (int c = 0; c < 128; c++) a += we2[k * 512 + h * 128 + c] * aedge2[h * 128 + c];
        g_aew2T[h * 64 + k] = a;
    } else if (i < 896) {                // ne1@w1: [3,128]
        int j = i - 512; int t = j >> 7, col = j & 127; float a = 0.f;
        for (int k = 0; k < 32; k++) a += ne1[t * 32 + k] * w1[k * 128 + col];
        g_ne1w1[j] = a;
    } else if (i < 2432) {               // ne2@w2: [3,512]
        int j = i - 896; int t = j >> 9, col = j & 511; float a = 0.f;
        for (int k = 0; k < 128; k++) a += ne2[t * 128 + k] * w2[k * 512 + col];
        g_ne2w2[j] = a;
    }
}

__global__ void k_pre_b(const float* __restrict__ ee1, const float* __restrict__ ee2) {
    int i = threadIdx.x;
    if (i < 16) {
        int t = i >> 2, h = i & 3; float a = 0.f;
        for (int k = 0; k < 64; k++) a += ee1[t * 64 + k] * g_aew1T[h * 64 + k];
        g_eea1[i] = a;
    } else if (i < 32) {
        int j = i - 16; int t = j >> 2, h = j & 3; float a = 0.f;
        for (int k = 0; k < 64; k++) a += ee2[t * 64 + k] * g_aew2T[h * 64 + k];
        g_eea2[j] = a;
    }
}

// ---------------- layer 1 GEMM v2: 128x128 tile, 8x8/thread, fused sd1 -----------
// h1 = x@w1 + (ne1@w1)[nt]; res1 = x@wres1 + b1; s/d = per-head dots of h1.
__global__ void __launch_bounds__(256, 2)
k_gemm1(const float* __restrict__ x, const int* __restrict__ nt,
        const float* __restrict__ w1, const float* __restrict__ wres1,
        const float* __restrict__ b1,
        const float* __restrict__ asrc, const float* __restrict__ adst, int N) {
    __shared__ __align__(16) float sXT[32][132];   // [k][r]
    __shared__ __align__(16) float sW[32][132];    // [k][c], reloaded per ct
    __shared__ float sA[128], sD[128];
    int t = threadIdx.x;           // 256
    int r0 = blockIdx.x * 128;
    int tc = t & 15, tr = t >> 4;

    for (int i = t; i < 128 * 32; i += 256) {
        int r = i >> 5, k = i & 31;
        int gr = r0 + r;
        sXT[k][r] = (gr < N) ? x[(size_t)gr * 32 + k] : 0.f;
    }
    if (t < 128) { sA[t] = asrc[t]; sD[t] = adst[t]; }

    for (int ct = 0; ct < 2; ct++) {
        __syncthreads();
        {
            const float* wp = ct ? wres1 : w1;
            for (int i = t; i < 32 * 32; i += 256) {
                int k = i >> 5, c4 = i & 31;
                *reinterpret_cast<float4*>(&sW[k][c4 * 4]) =
                    *reinterpret_cast<const float4*>(&wp[k * 128 + c4 * 4]);
            }
        }
        __syncthreads();
        uint64_t acc[8][4];
        #pragma unroll
        for (int j = 0; j < 8; j++)
            #pragma unroll
            for (int p = 0; p < 4; p++) acc[j][p] = 0ull;

        #pragma unroll 8
        for (int k = 0; k < 32; k++) {
            float4 xa = *reinterpret_cast<const float4*>(&sXT[k][tr * 8]);
            float4 xb = *reinterpret_cast<const float4*>(&sXT[k][tr * 8 + 4]);
            ulonglong2 wa = *reinterpret_cast<const ulonglong2*>(&sW[k][tc * 8]);
            ulonglong2 wb = *reinterpret_cast<const ulonglong2*>(&sW[k][tc * 8 + 4]);
            float xs[8] = {xa.x, xa.y, xa.z, xa.w, xb.x, xb.y, xb.z, xb.w};
            #pragma unroll
            for (int j = 0; j < 8; j++) {
                uint64_t x2 = pack2(xs[j], xs[j]);
                ffma2(acc[j][0], x2, wa.x);
                ffma2(acc[j][1], x2, wa.y);
                ffma2(acc[j][2], x2, wb.x);
                ffma2(acc[j][3], x2, wb.y);
            }
        }

        if (ct == 0) {
            float av[8], dv[8];
            #pragma unroll
            for (int i = 0; i < 8; i++) { av[i] = sA[tc * 8 + i]; dv[i] = sD[tc * 8 + i]; }
            int head = tc >> 2;
            #pragma unroll
            for (int j = 0; j < 8; j++) {
                int gr = r0 + tr * 8 + j;
                float o[8];
                #pragma unroll
                for (int p = 0; p < 4; p++) {
                    float2 u = unpack2(acc[j][p]);
                    o[2 * p] = u.x; o[2 * p + 1] = u.y;
                }
                int ty = (gr < N) ? nt[gr] : 0;
                const float* bias = &g_ne1w1[ty * 128 + tc * 8];
                float sp = 0.f, dp = 0.f;
                #pragma unroll
                for (int i = 0; i < 8; i++) {
                    o[i] += bias[i];
                    sp += o[i] * av[i];
                    dp += o[i] * dv[i];
                }
                sp += __shfl_xor_sync(0xffffffffu, sp, 1);
                sp += __shfl_xor_sync(0xffffffffu, sp, 2);
                dp += __shfl_xor_sync(0xffffffffu, dp, 1);
                dp += __shfl_xor_sync(0xffffffffu, dp, 2);
                if (gr < N) {
                    float* dst = &g_h1[(size_t)gr * 128 + tc * 8];
                    *reinterpret_cast<float4*>(dst)     = make_float4(o[0], o[1], o[2], o[3]);
                    *reinterpret_cast<float4*>(dst + 4) = make_float4(o[4], o[5], o[6], o[7]);
                    if ((tc & 3) == 0) { g_s[gr * 4 + head] = sp; g_d[gr * 4 + head] = dp; }
                }
            }
        } else {
            float bb[8];
            #pragma unroll
            for (int i = 0; i < 8; i++) bb[i] = b1[tc * 8 + i];
            #pragma unroll
            for (int j = 0; j < 8; j++) {
                int gr = r0 + tr * 8 + j; if (gr >= N) continue;
                float o[8];
                #pragma unroll
                for (int p = 0; p < 4; p++) {
                    float2 u = unpack2(acc[j][p]);
                    o[2 * p] = u.x; o[2 * p + 1] = u.y;
                }
                float* dst = &g_res[(size_t)gr * 128 + tc * 8];
                *reinterpret_cast<float4*>(dst) =
                    make_float4(o[0] + bb[0], o[1] + bb[1], o[2] + bb[2], o[3] + bb[3]);
                *reinterpret_cast<float4*>(dst + 4) =
                    make_float4(o[4] + bb[4], o[5] + bb[5], o[6] + bb[6], o[7] + bb[7]);
            }
        }
    }
}

// ---------------- edge pass A (layer 1) v2: 4 edges/warp, 8 lanes/edge -----------
__global__ void __launch_bounds__(256)
k_edgeA1(const int* __restrict__ src, const int* __restrict__ dst,
         const float* __restrict__ ea, const int* __restrict__ et, int E) {
    __shared__ __align__(16) float sa1[4][64], sa2[4][64];
    __shared__ float se1[16], se2[16];
    int t = threadIdx.x;  // 256
    sa1[t >> 6][t & 63] = g_aew1T[t];
    sa2[t >> 6][t & 63] = g_aew2T[t];
    if (t < 16) { se1[t] = g_eea1[t]; se2[t] = g_eea2[t]; }
    __syncthreads();
    int l = t & 31, sub = l >> 3, li = l & 7;
    int e = blockIdx.x * 32 + (t >> 5) * 4 + sub;
    bool valid = e < E;
    float e1[4] = {0, 0, 0, 0}, e2[4] = {0, 0, 0, 0};
    if (valid) {
        const float* row = ea + (size_t)e * 64 + li * 8;
        float4 va = *reinterpret_cast<const float4*>(row);
        float4 vb = *reinterpret_cast<const float4*>(row + 4);
        float vs[8] = {va.x, va.y, va.z, va.w, vb.x, vb.y, vb.z, vb.w};
        #pragma unroll
        for (int h = 0; h < 4; h++) {
            float4 w0 = *reinterpret_cast<const float4*>(&sa1[h][li * 8]);
            float4 w1v = *reinterpret_cast<const float4*>(&sa1[h][li * 8 + 4]);
            float4 u0 = *reinterpret_cast<const float4*>(&sa2[h][li * 8]);
            float4 u1 = *reinterpret_cast<const float4*>(&sa2[h][li * 8 + 4]);
            e1[h] = vs[0]*w0.x + vs[1]*w0.y + vs[2]*w0.z + vs[3]*w0.w
                  + vs[4]*w1v.x + vs[5]*w1v.y + vs[6]*w1v.z + vs[7]*w1v.w;
            e2[h] = vs[0]*u0.x + vs[1]*u0.y + vs[2]*u0.z + vs[3]*u0.w
                  + vs[4]*u1.x + vs[5]*u1.y + vs[6]*u1.z + vs[7]*u1.w;
        }
    }
    #pragma unroll
    for (int h = 0; h < 4; h++)
        #pragma unroll
        for (int o = 1; o < 8; o <<= 1) {
            e1[h] += __shfl_xor_sync(0xffffffffu, e1[h], o);
            e2[h] += __shfl_xor_sync(0xffffffffu, e2[h], o);
        }
    if (valid && li < 4) {
        float ev1 = (li == 0) ? e1[0] : (li == 1) ? e1[1] : (li == 2) ? e1[2] : e1[3];
        float ev2 = (li == 0) ? e2[0] : (li == 1) ? e2[1] : (li == 2) ? e2[2] : e2[3];
        int s_ = src[e], d_ = dst[e], ty = et[e];
        float a = g_s[s_ * 4 + li] + g_d[d_ * 4 + li] + ev1 + se1[ty * 4 + li];
        a = (a >= 0.f) ? a : 0.2f * a;
        g_alpha[e * 4 + li] = a;
        atomicMaxF(&g_amax[d_ * 4 + li], a);
        g_e2[e * 4 + li] = ev2 + se2[ty * 4 + li];
    }
}

// ---------------- edge pass B (both layers) ---------------------------------------
__global__ void k_passB(const int* __restrict__ dst, int E) {
    int i = blockIdx.x * blockDim.x + threadIdx.x;
    if (i >= E * 4) return;
    int e = i >> 2, h = i & 3; int d_ = dst[e];
    float ex = __expf(g_alpha[i] - g_amax[d_ * 4 + h]);
    g_alpha[i] = ex;
    atomicAdd(&g_den[d_ * 4 + h], ex);
}

// ---------------- edge aggregate layer 1 ------------------------------------------
__global__ void k_aggr1(const int* __restrict__ src, const int* __restrict__ dst, int E) {
    int e = blockIdx.x * 8 + (threadIdx.x >> 5); if (e >= E) return;
    int l = threadIdx.x & 31;
    int s_ = src[e], d_ = dst[e];
    float cf = 0.f;
    if (l < 4) cf = g_alpha[e * 4 + l] / (g_den[d_ * 4 + l] + 1e-16f);
    float coef = __shfl_sync(0xffffffffu, cf, l >> 3);  // head = (l*4)/32
    float4 hv = *reinterpret_cast<const float4*>(&g_h1[(size_t)s_ * 128 + l * 4]);
    red4(&g_acc1[(size_t)d_ * 128 + l * 4], hv.x * coef, hv.y * coef, hv.z * coef, hv.w * coef);
}

// ---------------- BN stats -----------------------------------------------------
__global__ void k_bnstats(int N) {
    int t = threadIdx.x;  // 128
    double s = 0.0, q = 0.0;
    for (int n = blockIdx.x; n < N; n += gridDim.x) {
        float y = g_acc1[(size_t)n * 128 + t] + g_res[(size_t)n * 128 + t];
        g_acc1[(size_t)n * 128 + t] = y;
        s += y; q += (double)y * y;
    }
    atomicAdd(&g_colsum[t], s);
    atomicAdd(&g_colsq[t], q);
}

__global__ void k_bnfin(const float* __restrict__ gamma, const float* __restrict__ beta, int N) {
    int t = threadIdx.x;
    double mu = g_colsum[t] / N;
    double var = g_colsq[t] / N - mu * mu;
    double sc = (double)gamma[t] / sqrt(var + 1e-5);
    g_scale[t] = (float)sc;
    g_shift[t] = (float)((double)beta[t] - mu * sc);
}

// ---------------- layer 2 GEMM: 128x128 tile, 8x8/thread, f32x2, fused sd2 --------
__global__ void __launch_bounds__(256, 2)
k_gemm2(const int* __restrict__ nt, const float* __restrict__ w2,
        const float* __restrict__ wres2, const float* __restrict__ b2,
        const float* __restrict__ asrc, const float* __restrict__ adst, int N) {
    extern __shared__ __align__(16) float sm[];
    float* sXT = sm;               // [k:128][r:132 pad]  (BN applied)
    float* sW  = sm + 128 * 132;   // [k:64][c:132 pad]
    int t = threadIdx.x;           // 256
    int r0 = blockIdx.x * 128;
    int tc = t & 15, tr = t >> 4;

    for (int i = t; i < 128 * 128; i += 256) {
        int r = i >> 7, k = i & 127; int gr = r0 + r;
        float v = 0.f;
        if (gr < N) v = g_acc1[(size_t)gr * 128 + k] * g_scale[k] + g_shift[k];
        sXT[k * 132 + r] = v;
    }

    for (int ct = 0; ct < 5; ct++) {
        uint64_t acc[8][4];
        #pragma unroll
        for (int j = 0; j < 8; j++)
            #pragma unroll
            for (int p = 0; p < 4; p++) acc[j][p] = 0ull;

        for (int kh = 0; kh < 2; kh++) {
            __syncthreads();
            for (int i = t; i < 64 * 32; i += 256) {
                int k = i >> 5, c4 = i & 31;
                float4 wv;
                if (ct < 4) wv = *reinterpret_cast<const float4*>(
                                 &w2[(size_t)(kh * 64 + k) * 512 + ct * 128 + c4 * 4]);
                else        wv = *reinterpret_cast<const float4*>(
                                 &wres2[(size_t)(kh * 64 + k) * 128 + c4 * 4]);
                *reinterpret_cast<float4*>(&sW[k * 132 + c4 * 4]) = wv;
            }
            __syncthreads();

            const float* xbase = sXT + kh * 64 * 132 + tr * 8;
            const float* wbase = sW + tc * 8;
            #pragma unroll 4
            for (int k = 0; k < 64; k++) {
                float4 xa = *reinterpret_cast<const float4*>(xbase + k * 132);
                float4 xb = *reinterpret_cast<const float4*>(xbase + k * 132 + 4);
                ulonglong2 wa = *reinterpret_cast<const ulonglong2*>(wbase + k * 132);
                ulonglong2 wb = *reinterpret_cast<const ulonglong2*>(wbase + k * 132 + 4);
                float xs[8] = {xa.x, xa.y, xa.z, xa.w, xb.x, xb.y, xb.z, xb.w};
                #pragma unroll
                for (int j = 0; j < 8; j++) {
                    uint64_t x2 = pack2(xs[j], xs[j]);
                    ffma2(acc[j][0], x2, wa.x);
                    ffma2(acc[j][1], x2, wa.y);
                    ffma2(acc[j][2], x2, wb.x);
                    ffma2(acc[j][3], x2, wb.y);
                }
            }
        }

        if (ct < 4) {
            float av[8], dv[8];
            #pragma unroll
            for (int i = 0; i < 8; i++) {
                av[i] = asrc[ct * 128 + tc * 8 + i];
                dv[i] = adst[ct * 128 + tc * 8 + i];
            }
            #pragma unroll
            for (int j = 0; j < 8; j++) {
                int gr = r0 + tr * 8 + j;
                float o[8];
                #pragma unroll
                for (int p = 0; p < 4; p++) {
                    float2 u = unpack2(acc[j][p]);
                    o[2 * p] = u.x; o[2 * p + 1] = u.y;
                }
                int ty = (gr < N) ? nt[gr] : 0;
                const float* bias = &g_ne2w2[ty * 512 + ct * 128 + tc * 8];
                float sp = 0.f, dp = 0.f;
                #pragma unroll
                for (int i = 0; i < 8; i++) {
                    o[i] += bias[i];
                    sp += o[i] * av[i];
                    dp += o[i] * dv[i];
                }
                #pragma unroll
                for (int off = 8; off; off >>= 1) {
                    sp += __shfl_xor_sync(0xffffffffu, sp, off);
                    dp += __shfl_xor_sync(0xffffffffu, dp, off);
                }
                if (gr < N) {
                    float* dst = &g_h2[(size_t)gr * 512 + ct * 128 + tc * 8];
                    *reinterpret_cast<float4*>(dst)     = make_float4(o[0], o[1], o[2], o[3]);
                    *reinterpret_cast<float4*>(dst + 4) = make_float4(o[4], o[5], o[6], o[7]);
                    if (tc == 0) { g_s[gr * 4 + ct] = sp; g_d[gr * 4 + ct] = dp; }
                }
            }
        } else {
            #pragma unroll
            for (int j = 0; j < 8; j++) {
                int gr = r0 + tr * 8 + j; if (gr >= N) continue;
                float o[8];
                #pragma unroll
                for (int p = 0; p < 4; p++) {
                    float2 u = unpack2(acc[j][p]);
                    o[2 * p] = u.x; o[2 * p + 1] = u.y;
                }
                const float* bias = &b2[tc * 8];
                float* dst = &g_res[(size_t)gr * 128 + tc * 8];
                *reinterpret_cast<float4*>(dst) =
                    make_float4(o[0] + bias[0], o[1] + bias[1], o[2] + bias[2], o[3] + bias[3]);
                *reinterpret_cast<float4*>(dst + 4) =
                    make_float4(o[4] + bias[4], o[5] + bias[5], o[6] + bias[6], o[7] + bias[7]);
            }
        }
    }
}

// ---------------- edge pass A (layer 2) --------------------------------------------
__global__ void k_edgeA2(const int* __restrict__ src, const int* __restrict__ dst, int E) {
    int i = blockIdx.x * blockDim.x + threadIdx.x;
    if (i >= E * 4) return;
    int e = i >> 2, h = i & 3;
    int s_ = src[e], d_ = dst[e];
    float a = g_s[s_ * 4 + h] + g_d[d_ * 4 + h] + g_e2[i];
    a = (a >= 0.f) ? a : 0.2f * a;
    g_alpha[i] = a;
    atomicMaxF(&g_amax[d_ * 4 + h], a);
}

// ---------------- edge aggregate layer 2 (head-mean fused) -------------------------
__global__ void k_aggr2(const int* __restrict__ src, const int* __restrict__ dst, int E) {
    int e = blockIdx.x * 8 + (threadIdx.x >> 5); if (e >= E) return;
    int l = threadIdx.x & 31;
    int s_ = src[e], d_ = dst[e];
    float cf = 0.f;
    if (l < 4) cf = 0.25f * g_alpha[e * 4 + l] / (g_den[d_ * 4 + l] + 1e-16f);
    float c0 = __shfl_sync(0xffffffffu, cf, 0);
    float c1 = __shfl_sync(0xffffffffu, cf, 1);
    float c2 = __shfl_sync(0xffffffffu, cf, 2);
    float c3 = __shfl_sync(0xffffffffu, cf, 3);
    const float4* hs = reinterpret_cast<const float4*>(&g_h2[(size_t)s_ * 512]);
    float4 h0 = hs[l], h1 = hs[32 + l], h2v = hs[64 + l], h3 = hs[96 + l];
    float mx = c0 * h0.x + c1 * h1.x + c2 * h2v.x + c3 * h3.x;
    float my = c0 * h0.y + c1 * h1.y + c2 * h2v.y + c3 * h3.y;
    float mz = c0 * h0.z + c1 * h1.z + c2 * h2v.z + c3 * h3.z;
    float mw = c0 * h0.w + c1 * h1.w + c2 * h2v.w + c3 * h3.w;
    red4(&g_acc2[(size_t)d_ * 128 + l * 4], mx, my, mz, mw);
}

// ---------------- final: out = acc2 + res2 -----------------------------------------
__global__ void k_final(float4* __restrict__ out, int N) {
    int i = blockIdx.x * blockDim.x + threadIdx.x;
    if (i >= N * 32) return;
    const float4 a = reinterpret_cast<const float4*>(g_acc2)[i];
    const float4 r = reinterpret_cast<const float4*>(g_res)[i];
    out[i] = make_float4(a.x + r.x, a.y + r.y, a.z + r.z, a.w + r.w);
}

// ---------------- host launch ----------------------------------------------------
extern "C" void kernel_launch(void* const* d_in, const int* in_sizes, int n_in,
                              void* d_out, int out_size) {
    const float* x      = (const float*)d_in[0];
    const int*   ei     = (const int*)  d_in[1];
    const int*   nt     = (const int*)  d_in[2];
    const float* ea     = (const float*)d_in[3];
    const int*   et     = (const int*)  d_in[4];
    const float* ne1    = (const float*)d_in[5];
    const float* w1     = (const float*)d_in[6];
    const float* we1    = (const float*)d_in[7];
    const float* asrc1  = (const float*)d_in[8];
    const float* adst1  = (const float*)d_in[9];
    const float* aedge1 = (const float*)d_in[10];
    const float* ee1    = (const float*)d_in[11];
    const float* wres1  = (const float*)d_in[12];
    const float* b1     = (const float*)d_in[13];
    const float* gamma  = (const float*)d_in[14];
    const float* beta   = (const float*)d_in[15];
    const float* ne2    = (const float*)d_in[16];
    const float* w2     = (const float*)d_in[17];
    const float* we2    = (const float*)d_in[18];
    const float* asrc2  = (const float*)d_in[19];
    const float* adst2  = (const float*)d_in[20];
    const float* aedge2 = (const float*)d_in[21];
    const float* ee2    = (const float*)d_in[22];
    const float* wres2  = (const float*)d_in[23];
    const float* b2     = (const float*)d_in[24];

    int N = in_sizes[0] / 32;
    int E = in_sizes[4];
    const int* src = ei;
    const int* dstp = ei + E;

    // ---- init + precompute ----
    k_init1<<<1024, 256>>>(N);
    k_pre_a<<<10, 256>>>(we1, aedge1, we2, aedge2, ne1, w1, ne2, w2);
    k_pre_b<<<1, 32>>>(ee1, ee2);

    // ---- layer 1 ----
    k_gemm1<<<(N + 127) / 128, 256>>>(x, nt, w1, wres1, b1, asrc1, adst1, N);
    k_edgeA1<<<(E + 31) / 32, 256>>>(src, dstp, ea, et, E);
    k_passB<<<(E * 4 + 255) / 256, 256>>>(dstp, E);
    k_aggr1<<<(E + 7) / 8, 256>>>(src, dstp, E);

    // ---- batch norm ----
    k_bnstats<<<592, 128>>>(N);
    k_bnfin<<<1, 128>>>(gamma, beta, N);

    // ---- layer 2 ----
    size_t smem = (128 * 132 + 64 * 132) * sizeof(float);  // 101376 B
    cudaFuncSetAttribute(k_gemm2, cudaFuncAttributeMaxDynamicSharedMemorySize, (int)smem);
    k_gemm2<<<(N + 127) / 128, 256, smem>>>(nt, w2, wres2, b2, asrc2, adst2, N);
    k_init2<<<1024, 256>>>(N);
    k_edgeA2<<<(E * 4 + 255) / 256, 256>>>(src, dstp, E);
    k_passB<<<(E * 4 + 255) / 256, 256>>>(dstp, E);
    k_aggr2<<<(E + 7) / 8, 256>>>(src, dstp, E);

    // ---- epilogue ----
    k_final<<<(N * 32 + 255) / 256, 256>>>((float4*)d_out, N);
}